// round 15
// baseline (speedup 1.0000x reference)
#include <cuda_runtime.h>
#include <cuda_bf16.h>
#include <math.h>
#include <stdint.h>

// Problem dims
#define BB 4096
#define UU 256
#define DD 128

// Fused kernel: grid (8 ntile8, 32 mtiles) = 256 CTAs, 2 CTAs/SM.
// CTA tile: 128 rows x 64 paired cols (32 u).
// Phase 1: convert x rows + W/bias cols -> smem bf16 images (hi/lo dedup,
//          4 physical chunks each), nv2 + cons in smem. No global images.
// Phase 2: all-K-resident dual GEMM (K = 3*128 via pa/pb chunk maps).
// Phase 3: e = 2^logit epilogue + per-row partial sums -> g_part8.
// Scale kernel: out = e / rowsum.
#define SM_A 0                    // 4 x 16KB A chunks (128 rows x 64 bf16)
#define SM_B 65536                // 4 x 8KB B chunks (64 paired cols)
#define SM_SUM 98304              // 128 rows x 2 floats
#define SM_NV2 99328              // 128 floats
#define SM_CONS 99840             // 32 float4
#define FUSED_SMEM 100352

__device__ float g_e[BB * UU];          // 4 MB: e = 2^logit
__device__ float g_part8[BB * 8];       // per-row partial sums (8 ntiles)

// ---------------------------------------------------------------------------
// PTX helpers
// ---------------------------------------------------------------------------
__device__ __forceinline__ uint32_t smem_u32(const void* p) {
    uint32_t a;
    asm("{ .reg .u64 t; cvta.to.shared.u64 t, %1; cvt.u32.u64 %0, t; }"
        : "=r"(a) : "l"(p));
    return a;
}
#define LDSM4(r0, r1, r2, r3, addr) \
    asm volatile("ldmatrix.sync.aligned.m8n8.x4.shared.b16 {%0,%1,%2,%3}, [%4];" \
                 : "=r"(r0), "=r"(r1), "=r"(r2), "=r"(r3) : "r"(addr))
#define MMA16816(d0, d1, d2, d3, a0, a1, a2, a3, b0, b1) \
    asm volatile("mma.sync.aligned.m16n8k16.row.col.f32.bf16.bf16.f32 " \
                 "{%0,%1,%2,%3}, {%4,%5,%6,%7}, {%8,%9}, {%0,%1,%2,%3};" \
                 : "+f"(d0), "+f"(d1), "+f"(d2), "+f"(d3) \
                 : "r"(a0), "r"(a1), "r"(a2), "r"(a3), "r"(b0), "r"(b1))

__device__ __forceinline__ float fast_sqrt(float v) {
    float r;
    asm("sqrt.approx.f32 %0, %1;" : "=f"(r) : "f"(v));
    return r;
}

// packed hi/lo bf16 split
__device__ __forceinline__ void split8p(const float4 a, const float4 b,
                                        uint4& hq, uint4& lq) {
    float vf[8] = {a.x, a.y, a.z, a.w, b.x, b.y, b.z, b.w};
    uint32_t h[4], l[4];
    float lo[8];
    #pragma unroll
    for (int i = 0; i < 4; i++) {
        __nv_bfloat162 hb = __float22bfloat162_rn(make_float2(vf[2*i], vf[2*i+1]));
        uint32_t bits = *reinterpret_cast<uint32_t*>(&hb);
        h[i] = bits;
        lo[2*i]   = vf[2*i]   - __uint_as_float(bits << 16);
        lo[2*i+1] = vf[2*i+1] - __uint_as_float(bits & 0xFFFF0000u);
    }
    #pragma unroll
    for (int i = 0; i < 4; i++) {
        __nv_bfloat162 lb = __float22bfloat162_rn(make_float2(lo[2*i], lo[2*i+1]));
        l[i] = *reinterpret_cast<uint32_t*>(&lb);
    }
    hq = make_uint4(h[0], h[1], h[2], h[3]);
    lq = make_uint4(l[0], l[1], l[2], l[3]);
}
__device__ __forceinline__ float dot8(const float4 a, const float4 b) {
    return a.x * a.x + a.y * a.y + a.z * a.z + a.w * a.w
         + b.x * b.x + b.y * b.y + b.z * b.z + b.w * b.w;
}

// e = 2^(hyperbolic logit); |logit| = O(5), max-free softmax is safe
__device__ __forceinline__ float elogit_f(float xw, float xb, float nv2,
                                          float nb2, float bw, float sww) {
    float beta = 1.0f - nb2;
    float bsw  = beta * sww;
    float t2 = -2.0f * xb;
    float alpha = 1.0f + t2 + nv2;
    float dd = 1.0f + t2 + nb2 * nv2;
    float num = 2.0f * beta * (beta * xw - alpha * bw);
    float smm_num = alpha * alpha * nb2 - 2.0f * alpha * beta * xb
                    + beta * beta * nv2;
    float arg = __fdividef(num * dd, (dd * dd - smm_num) * bsw);
    float s = arg + fast_sqrt(fmaf(arg, arg, 1.0f));
    return exp2f((2.0f * sww) * __log2f(s));
}

// ---------------------------------------------------------------------------
// Fused: conversion + dual GEMM + e-epilogue. grid (8, 32), block 256.
// ---------------------------------------------------------------------------
__global__ void __launch_bounds__(256, 2)
fused_kernel(const float* __restrict__ x,
             const float* __restrict__ W,
             const float* __restrict__ bias) {
    extern __shared__ __align__(1024) char smem[];
    uint32_t sbase = smem_u32(smem);
    float*  ssum  = reinterpret_cast<float*>(smem + SM_SUM);    // [128][2]
    float*  snv2  = reinterpret_cast<float*>(smem + SM_NV2);    // [128]
    float4* scons = reinterpret_cast<float4*>(smem + SM_CONS);  // [32]

    const int tid = threadIdx.x;
    const int wid = tid >> 5, lane = tid & 31;
    const int ntile8 = blockIdx.x, mtile = blockIdx.y;

    // ===== Phase 1a: x rows (128) -> A smem + nv2. 8 tasks/thread =====
    {
        const float4* x4 = reinterpret_cast<const float4*>(x) + (mtile * 128) * 32;
        #pragma unroll
        for (int i = 0; i < 8; i++) {
            int t = i * 256 + tid;
            int rl = t >> 4, kg = t & 15;
            int half = kg >> 3, k16 = kg & 7;
            float4 a = x4[rl * 32 + kg * 2];
            float4 b = x4[rl * 32 + kg * 2 + 1];
            uint4 hq, lq;
            split8p(a, b, hq, lq);
            float s = dot8(a, b);
            #pragma unroll
            for (int sh = 8; sh > 0; sh >>= 1)
                s += __shfl_xor_sync(0xffffffffu, s, sh);
            if (kg == 0) snv2[rl] = s;
            int off16 = (rl >> 3) * 64 + (rl & 7) * 8 + (k16 ^ (rl & 7));
            *reinterpret_cast<uint4*>(smem + SM_A + (half * 1024 + off16) * 16) = hq;
            *reinterpret_cast<uint4*>(smem + SM_A + ((2 + half) * 1024 + off16) * 16) = lq;
        }
    }

    // ===== Phase 1b: 32 u of W/bias -> B smem (paired cols) + cons =====
    {
        #pragma unroll
        for (int i = 0; i < 2; i++) {
            int t = i * 256 + tid;
            int ul = t >> 4, kg = t & 15;
            int u  = ntile8 * 32 + ul;
            int half = kg >> 3, k16 = kg & 7;
            const float4* W4 = reinterpret_cast<const float4*>(W) + u * 32 + kg * 2;
            const float4* B4 = reinterpret_cast<const float4*>(bias) + u * 32 + kg * 2;
            float4 wa = W4[0], wb = W4[1];
            float4 ba = B4[0], bb = B4[1];

            float nb2 = dot8(ba, bb);
            float ww  = dot8(wa, wb);
            float bw  = ba.x * wa.x + ba.y * wa.y + ba.z * wa.z + ba.w * wa.w
                      + bb.x * wb.x + bb.y * wb.y + bb.z * wb.z + bb.w * wb.w;
            #pragma unroll
            for (int sh = 8; sh > 0; sh >>= 1) {
                nb2 += __shfl_xor_sync(0xffffffffu, nb2, sh);
                bw  += __shfl_xor_sync(0xffffffffu, bw,  sh);
                ww  += __shfl_xor_sync(0xffffffffu, ww,  sh);
            }
            if (kg == 0) scons[ul] = make_float4(nb2, bw, sqrtf(ww), 0.0f);

            uint4 whq, wlq, bhq, blq;
            split8p(wa, wb, whq, wlq);
            split8p(ba, bb, bhq, blq);
            {
                int nloc = 2 * ul;               // W -> even col
                int off16 = (nloc >> 3) * 64 + (nloc & 7) * 8 + (k16 ^ (nloc & 7));
                *reinterpret_cast<uint4*>(smem + SM_B + (half * 512 + off16) * 16) = whq;
                *reinterpret_cast<uint4*>(smem + SM_B + ((2 + half) * 512 + off16) * 16) = wlq;
            }
            {
                int nloc = 2 * ul + 1;           // bias -> odd col
                int off16 = (nloc >> 3) * 64 + (nloc & 7) * 8 + (k16 ^ (nloc & 7));
                *reinterpret_cast<uint4*>(smem + SM_B + (half * 512 + off16) * 16) = bhq;
                *reinterpret_cast<uint4*>(smem + SM_B + ((2 + half) * 512 + off16) * 16) = blq;
            }
        }
    }
    __syncthreads();

    // ===== Phase 2: mainloop, all data resident, no barriers =====
    const int m0 = (wid & 3) * 32;            // 4 m-warps
    const int n0 = (wid >> 2) * 32;           // 2 n-warps (cols)
    const int rowa  = m0 + (lane & 15);
    const int abase = (rowa >> 3) * 64 + (rowa & 7) * 8;
    const int aswz  = rowa & 7;
    const int akus  = lane >> 4;
    const int rowb  = n0 + (lane & 7) + ((lane >> 4) << 3);
    const int bbase = (rowb >> 3) * 64 + (rowb & 7) * 8;
    const int bswz  = rowb & 7;
    const int bkus  = (lane >> 3) & 1;

    float d[2][4][4];
    #pragma unroll
    for (int i = 0; i < 2; i++)
        #pragma unroll
        for (int j = 0; j < 4; j++)
            #pragma unroll
            for (int q = 0; q < 4; q++) d[i][j][q] = 0.0f;

    const int pa[6] = {0, 1, 0, 1, 2, 3};     // A chunks: hi0 hi1 hi0 hi1 lo0 lo1
    const int pb[6] = {0, 1, 2, 3, 0, 1};     // B chunks: hi0 hi1 lo0 lo1 hi0 hi1

    #pragma unroll
    for (int l = 0; l < 6; l++) {
        uint32_t aB = sbase + SM_A + pa[l] * 16384;
        uint32_t bB = sbase + SM_B + pb[l] * 8192;

        #pragma unroll
        for (int kk = 0; kk < 4; kk++) {
            uint32_t af[2][4];
            #pragma unroll
            for (int mf = 0; mf < 2; mf++) {
                uint32_t addr = aB + ((abase + mf * 128 +
                                       ((2 * kk + akus) ^ aswz)) << 4);
                LDSM4(af[mf][0], af[mf][1], af[mf][2], af[mf][3], addr);
            }
            uint32_t bf[2][4];
            #pragma unroll
            for (int h = 0; h < 2; h++) {
                uint32_t addr = bB + ((bbase + h * 128 +
                                       ((2 * kk + bkus) ^ bswz)) << 4);
                LDSM4(bf[h][0], bf[h][1], bf[h][2], bf[h][3], addr);
            }
            #pragma unroll
            for (int mf = 0; mf < 2; mf++)
                #pragma unroll
                for (int nf = 0; nf < 4; nf++)
                    MMA16816(d[mf][nf][0], d[mf][nf][1], d[mf][nf][2], d[mf][nf][3],
                             af[mf][0], af[mf][1], af[mf][2], af[mf][3],
                             bf[nf >> 1][(nf & 1) * 2], bf[nf >> 1][(nf & 1) * 2 + 1]);
        }
    }

    // ===== Phase 3: e = 2^logit + per-row partial sums =====
    const int rloc0 = m0 + (lane >> 2);
    const int rbase = mtile * 128 + rloc0;
    const int ul0   = (wid >> 2) * 16 + (lane & 3);   // local u 0..31
    const int ubase = ntile8 * 32 + ul0;

    float4 cons[4];
    #pragma unroll
    for (int nf = 0; nf < 4; nf++)
        cons[nf] = scons[ul0 + nf * 4];
    float nv2a[2], nv2b[2];
    #pragma unroll
    for (int mf = 0; mf < 2; mf++) {
        nv2a[mf] = snv2[rloc0 + mf * 16];
        nv2b[mf] = snv2[rloc0 + mf * 16 + 8];
    }

    float sa[2], sb2[2];
    #pragma unroll
    for (int mf = 0; mf < 2; mf++) { sa[mf] = 0.0f; sb2[mf] = 0.0f; }

    #pragma unroll
    for (int mf = 0; mf < 2; mf++)
        #pragma unroll
        for (int nf = 0; nf < 4; nf++) {
            int u = ubase + nf * 4;
            float4 cs = cons[nf];
            float ea = elogit_f(d[mf][nf][0], d[mf][nf][1], nv2a[mf],
                                cs.x, cs.y, cs.z);
            float eb = elogit_f(d[mf][nf][2], d[mf][nf][3], nv2b[mf],
                                cs.x, cs.y, cs.z);
            g_e[(rbase + mf * 16) * UU + u] = ea;
            g_e[(rbase + mf * 16 + 8) * UU + u] = eb;
            sa[mf] += ea;
            sb2[mf] += eb;
        }

    #pragma unroll
    for (int mf = 0; mf < 2; mf++) {
        sa[mf]  += __shfl_xor_sync(0xffffffffu, sa[mf],  1);
        sa[mf]  += __shfl_xor_sync(0xffffffffu, sa[mf],  2);
        sb2[mf] += __shfl_xor_sync(0xffffffffu, sb2[mf], 1);
        sb2[mf] += __shfl_xor_sync(0xffffffffu, sb2[mf], 2);
    }
    const int wn = wid >> 2;
    if ((lane & 3) == 0) {
        #pragma unroll
        for (int mf = 0; mf < 2; mf++) {
            int rl = m0 + mf * 16 + (lane >> 2);
            ssum[rl * 2 + wn] = sa[mf];
            ssum[(rl + 8) * 2 + wn] = sb2[mf];
        }
    }
    __syncthreads();
    if (tid < 128) {
        float2 v = reinterpret_cast<float2*>(ssum)[tid];
        g_part8[(mtile * 128 + tid) * 8 + ntile8] = v.x + v.y;
    }
}

// ---------------------------------------------------------------------------
// Scale: out = e / rowsum. Pure elementwise. grid 2048, block 256 (2 rows).
// ---------------------------------------------------------------------------
__global__ void __launch_bounds__(256)
scale_kernel(float* __restrict__ out) {
    const int tid = threadIdx.x;
    const int row = blockIdx.x * 2 + (tid >> 7);
    const int c2  = tid & 127;

    float4 p0 = reinterpret_cast<float4*>(g_part8)[row * 2];
    float4 p1 = reinterpret_cast<float4*>(g_part8)[row * 2 + 1];
    float inv = __fdividef(1.0f, p0.x + p0.y + p0.z + p0.w
                               + p1.x + p1.y + p1.z + p1.w);
    const float2* e2 = reinterpret_cast<const float2*>(g_e) + row * 128;
    float2 v = e2[c2];
    v.x *= inv;
    v.y *= inv;
    reinterpret_cast<float2*>(out)[row * 128 + c2] = v;
}

// ---------------------------------------------------------------------------
extern "C" void kernel_launch(void* const* d_in, const int* in_sizes, int n_in,
                              void* d_out, int out_size) {
    const float* x    = (const float*)d_in[0];
    const float* W    = (const float*)d_in[1];
    const float* bias = (const float*)d_in[2];
    float* out = (float*)d_out;

    cudaFuncSetAttribute(fused_kernel,
                         cudaFuncAttributeMaxDynamicSharedMemorySize, FUSED_SMEM);

    fused_kernel<<<dim3(8, 32), 256, FUSED_SMEM>>>(x, W, bias);
    scale_kernel<<<BB / 2, 256>>>(out);
}

// round 16
// speedup vs baseline: 1.6243x; 1.6243x over previous
#include <cuda_runtime.h>
#include <cuda_bf16.h>
#include <math.h>
#include <stdint.h>

// Problem dims
#define BB 4096
#define UU 256
#define DD 128

// GEMM: C[4096, 512] = A[4096, 384]bf16 . B[512, 384]bf16^T, fp32 accum
// K = 3*128 (hi*hi, hi*lo, lo*hi). B columns PAIR-interleaved: col 2u = W_u,
// col 2u+1 = bias_u, so each MMA (d0,d1) = (xw, xb) for one u.
// Epilogue (hyperbolic logit, base-2) fused in-register -> g_logits.
// Softmax kernel: max-free (|logit| = O(5)), one warp per row.
#define NCHUNK 6                 // K chunks of 64 bf16
#define A_CH_U4 1024             // 128 rows x 64 bf16 = 16KB per chunk (uint4)
#define A_MT_U4 (NCHUNK * A_CH_U4)
#define B_NT_U4 (NCHUNK * A_CH_U4)
#define GEMM_SMEM 196608         // all-K: A 96KB + B 96KB

__device__ float4 g_cons[UU];            // {nb2, bw, sqrt(ww), 0}
__device__ float  g_nv2[BB];
__device__ uint4  g_A[32 * A_MT_U4];     // 3 MB pre-swizzled A (32 mtiles)
__device__ uint4  g_B[4 * B_NT_U4];      // 384 KB pre-swizzled B (4 ntiles)
__device__ float  g_logits[BB * UU];     // 4 MB logits (base-2 scaled)

// ---------------------------------------------------------------------------
// PTX helpers (sm_80-compatible only: cp.async, ldmatrix, mma.sync)
// ---------------------------------------------------------------------------
__device__ __forceinline__ uint32_t smem_u32(const void* p) {
    uint32_t a;
    asm("{ .reg .u64 t; cvta.to.shared.u64 t, %1; cvt.u32.u64 %0, t; }"
        : "=r"(a) : "l"(p));
    return a;
}
#define CP16(dst, src) \
    asm volatile("cp.async.cg.shared.global [%0], [%1], 16;" \
                 :: "r"(dst), "l"(src) : "memory")
#define CP_COMMIT() asm volatile("cp.async.commit_group;" ::: "memory")
#define CP_WAITG(n) asm volatile("cp.async.wait_group " #n ";" ::: "memory")
#define LDSM4(r0, r1, r2, r3, addr) \
    asm volatile("ldmatrix.sync.aligned.m8n8.x4.shared.b16 {%0,%1,%2,%3}, [%4];" \
                 : "=r"(r0), "=r"(r1), "=r"(r2), "=r"(r3) : "r"(addr))
#define MMA16816(d0, d1, d2, d3, a0, a1, a2, a3, b0, b1) \
    asm volatile("mma.sync.aligned.m16n8k16.row.col.f32.bf16.bf16.f32 " \
                 "{%0,%1,%2,%3}, {%4,%5,%6,%7}, {%8,%9}, {%0,%1,%2,%3};" \
                 : "+f"(d0), "+f"(d1), "+f"(d2), "+f"(d3) \
                 : "r"(a0), "r"(a1), "r"(a2), "r"(a3), "r"(b0), "r"(b1))

__device__ __forceinline__ float fast_sqrt(float v) {
    float r;
    asm("sqrt.approx.f32 %0, %1;" : "=f"(r) : "f"(v));
    return r;
}
__device__ __forceinline__ float fast_ex2(float v) {
    float r;
    asm("ex2.approx.f32 %0, %1;" : "=f"(r) : "f"(v));
    return r;
}

__device__ __forceinline__ void split_bf16(float v, __nv_bfloat16& hi, __nv_bfloat16& lo) {
    hi = __float2bfloat16(v);
    lo = __float2bfloat16(v - __bfloat162float(hi));
}

// hyperbolic logit (base-2 scaled); identical math to validated epilogue
__device__ __forceinline__ float logit_f(float xw, float xb, float nv2,
                                         float nb2, float bw, float sww) {
    float beta = 1.0f - nb2;
    float bsw  = beta * sww;
    float t2 = -2.0f * xb;
    float alpha = 1.0f + t2 + nv2;
    float dd = 1.0f + t2 + nb2 * nv2;
    float num = 2.0f * beta * (beta * xw - alpha * bw);
    float smm_num = alpha * alpha * nb2 - 2.0f * alpha * beta * xb
                    + beta * beta * nv2;
    float arg = __fdividef(num * dd, (dd * dd - smm_num) * bsw);
    float s = arg + fast_sqrt(fmaf(arg, arg, 1.0f));
    return (2.0f * sww) * __log2f(s);
}

// ---------------------------------------------------------------------------
// Merged prep: blocks 0-255 do A (x split + nv2), blocks 256-511 do W/bias.
// (byte-identical to the 16.9us-measured round)
// ---------------------------------------------------------------------------
__global__ void prep_kernel(const float* __restrict__ x,
                            const float* __restrict__ W,
                            const float* __restrict__ bias) {
    const int tid = threadIdx.x;
    if (blockIdx.x < 256) {
        // ---- prepA: 16 rows per block ----
        int r  = tid >> 4;
        int kg = tid & 15;
        int row = blockIdx.x * 16 + r;

        const float4* x4 = reinterpret_cast<const float4*>(x) + row * 32 + kg * 2;
        float4 a = x4[0], c = x4[1];
        float v[8] = {a.x, a.y, a.z, a.w, c.x, c.y, c.z, c.w};

        float s = 0.0f;
        union { __nv_bfloat16 h[8]; uint4 q; } hi, lo;
        #pragma unroll
        for (int i = 0; i < 8; i++) {
            s += v[i] * v[i];
            split_bf16(v[i], hi.h[i], lo.h[i]);
        }
        #pragma unroll
        for (int sh = 8; sh > 0; sh >>= 1)
            s += __shfl_xor_sync(0xffffffffu, s, sh);
        if (kg == 0) g_nv2[row] = s;

        int mtile = row >> 7, rloc = row & 127;
        int half = kg >> 3, k16 = kg & 7;
        int off16 = (rloc >> 3) * 64 + (rloc & 7) * 8 + (k16 ^ (rloc & 7));
        uint4* base = g_A + mtile * A_MT_U4;
        base[(half)     * A_CH_U4 + off16] = hi.q;   // hi (pairs B hi)
        base[(2 + half) * A_CH_U4 + off16] = hi.q;   // hi (pairs B lo)
        base[(4 + half) * A_CH_U4 + off16] = lo.q;   // lo (pairs B hi)
    } else {
        // ---- prepWB: one u per block ----
        int u = blockIdx.x - 256;
        int k = tid;
        __shared__ float sw[DD], sb[DD];
        __shared__ float red[3][4];

        if (k < DD) {
            float b = bias[u * DD + k];
            float w = W[u * DD + k];
            sw[k] = w;
            sb[k] = b;
            float nb2 = b * b, bw = b * w, ww = w * w;
            #pragma unroll
            for (int s = 16; s > 0; s >>= 1) {
                nb2 += __shfl_xor_sync(0xffffffffu, nb2, s);
                bw  += __shfl_xor_sync(0xffffffffu, bw,  s);
                ww  += __shfl_xor_sync(0xffffffffu, ww,  s);
            }
            int wid = k >> 5, lane = k & 31;
            if (lane == 0) { red[0][wid] = nb2; red[1][wid] = bw; red[2][wid] = ww; }
        }
        __syncthreads();
        if (k == 0) {
            float n2  = red[0][0] + red[0][1] + red[0][2] + red[0][3];
            float bw_ = red[1][0] + red[1][1] + red[1][2] + red[1][3];
            float ww_ = red[2][0] + red[2][1] + red[2][2] + red[2][3];
            g_cons[u] = make_float4(n2, bw_, sqrtf(ww_), 0.0f);
        }
        if (k < 32) {
            int which = k >> 4;      // 0 = W (even col), 1 = bias (odd col)
            int kg    = k & 15;
            const float* s = which ? sb : sw;
            union { __nv_bfloat16 h[8]; uint4 v; } hi, lo;
            #pragma unroll
            for (int i = 0; i < 8; i++)
                split_bf16(s[kg * 8 + i], hi.h[i], lo.h[i]);

            int n = 2 * u + which;               // PAIRED layout
            int ntile = n >> 7, nloc = n & 127;
            int half = kg >> 3, k16 = kg & 7;
            int off16 = (nloc >> 3) * 64 + (nloc & 7) * 8 + (k16 ^ (nloc & 7));
            uint4* base = g_B + ntile * B_NT_U4;
            base[(half)     * A_CH_U4 + off16] = hi.v;
            base[(2 + half) * A_CH_U4 + off16] = lo.v;
            base[(4 + half) * A_CH_U4 + off16] = hi.v;
        }
    }
}

// ---------------------------------------------------------------------------
// GEMM + fused hyperbolic epilogue: grid (4, 32), block 256 (8 warps).
// CTA 128x128 (= 128 rows x 64 u). Writes logits to g_logits.
// (byte-identical to the 16.9us-measured round)
// ---------------------------------------------------------------------------
__global__ void __launch_bounds__(256)
gemm_kernel() {
    extern __shared__ __align__(1024) char smem[];
    uint32_t sbase = smem_u32(smem);
    const int tid = threadIdx.x;
    const int wid = tid >> 5, lane = tid & 31;
    const int ntile = blockIdx.x, mtile = blockIdx.y;

    const uint4* gA = g_A + mtile * A_MT_U4;
    const uint4* gB = g_B + ntile * B_NT_U4;

    #pragma unroll
    for (int c = 0; c < NCHUNK; c++) {
        uint32_t dA = sbase + c * 16384;
        uint32_t dB = sbase + 98304 + c * 16384;
        const uint4* sa = gA + c * A_CH_U4;
        const uint4* sb = gB + c * A_CH_U4;
        #pragma unroll
        for (int i = 0; i < 4; i++) CP16(dA + (tid + 256 * i) * 16, sa + tid + 256 * i);
        #pragma unroll
        for (int i = 0; i < 4; i++) CP16(dB + (tid + 256 * i) * 16, sb + tid + 256 * i);
        CP_COMMIT();
    }

    const int m0 = (wid & 1) * 64;
    const int n0 = (wid >> 1) * 32;
    const int rowa  = m0 + (lane & 15);
    const int abase = (rowa >> 3) * 64 + (rowa & 7) * 8;
    const int aswz  = rowa & 7;
    const int akus  = lane >> 4;
    const int rowb  = n0 + (lane & 7) + ((lane >> 4) << 3);
    const int bbase = (rowb >> 3) * 64 + (rowb & 7) * 8;
    const int bswz  = rowb & 7;
    const int bkus  = (lane >> 3) & 1;

    float d[4][4][4];
    #pragma unroll
    for (int i = 0; i < 4; i++)
        #pragma unroll
        for (int j = 0; j < 4; j++)
            #pragma unroll
            for (int q = 0; q < 4; q++) d[i][j][q] = 0.0f;

    #pragma unroll
    for (int c = 0; c < NCHUNK; c++) {
        switch (c) {
            case 0: CP_WAITG(5); break;
            case 1: CP_WAITG(4); break;
            case 2: CP_WAITG(3); break;
            case 3: CP_WAITG(2); break;
            case 4: CP_WAITG(1); break;
            default: CP_WAITG(0); break;
        }
        __syncthreads();

        uint32_t aB = sbase + c * 16384;
        uint32_t bB = sbase + 98304 + c * 16384;

        #pragma unroll
        for (int kk = 0; kk < 4; kk++) {
            uint32_t af[4][4];
            #pragma unroll
            for (int mf = 0; mf < 4; mf++) {
                uint32_t addr = aB + ((abase + mf * 128 +
                                       ((2 * kk + akus) ^ aswz)) << 4);
                LDSM4(af[mf][0], af[mf][1], af[mf][2], af[mf][3], addr);
            }
            uint32_t bf[2][4];
            #pragma unroll
            for (int h = 0; h < 2; h++) {
                uint32_t addr = bB + ((bbase + h * 128 +
                                       ((2 * kk + bkus) ^ bswz)) << 4);
                LDSM4(bf[h][0], bf[h][1], bf[h][2], bf[h][3], addr);
            }
            #pragma unroll
            for (int mf = 0; mf < 4; mf++)
                #pragma unroll
                for (int nf = 0; nf < 4; nf++)
                    MMA16816(d[mf][nf][0], d[mf][nf][1], d[mf][nf][2], d[mf][nf][3],
                             af[mf][0], af[mf][1], af[mf][2], af[mf][3],
                             bf[nf >> 1][(nf & 1) * 2], bf[nf >> 1][(nf & 1) * 2 + 1]);
        }
    }

    // ---- fused epilogue: (d0,d1) = (xw,xb) for u; (d2,d3) same u, row+8 ----
    const int rbase = mtile * 128 + m0 + (lane >> 2);
    const int ubase = ntile * 64 + (wid >> 1) * 16 + (lane & 3);

    float4 cons[4];
    #pragma unroll
    for (int nf = 0; nf < 4; nf++)
        cons[nf] = g_cons[ubase + nf * 4];
    float nv2a[4], nv2b[4];
    #pragma unroll
    for (int mf = 0; mf < 4; mf++) {
        nv2a[mf] = g_nv2[rbase + mf * 16];
        nv2b[mf] = g_nv2[rbase + mf * 16 + 8];
    }

    #pragma unroll
    for (int mf = 0; mf < 4; mf++)
        #pragma unroll
        for (int nf = 0; nf < 4; nf++) {
            int u = ubase + nf * 4;
            float4 cs = cons[nf];
            g_logits[(rbase + mf * 16) * UU + u] =
                logit_f(d[mf][nf][0], d[mf][nf][1], nv2a[mf], cs.x, cs.y, cs.z);
            g_logits[(rbase + mf * 16 + 8) * UU + u] =
                logit_f(d[mf][nf][2], d[mf][nf][3], nv2b[mf], cs.x, cs.y, cs.z);
        }
}

// ---------------------------------------------------------------------------
// Softmax (base-2, MAX-FREE): one warp per row. grid 512, block 256.
// |logit| = O(5) (validated R9/R10), so exp2 directly — no max pass, the
// exp2s issue as soon as each load lands.
// ---------------------------------------------------------------------------
__global__ void __launch_bounds__(256)
softmax_kernel(float* __restrict__ out) {
    const int wid = threadIdx.x >> 5, lane = threadIdx.x & 31;
    const int row = blockIdx.x * 8 + wid;

    const float* lrow = g_logits + row * UU;
    float e[8];
    float s = 0.0f;
    #pragma unroll
    for (int j = 0; j < 8; j++) {
        e[j] = fast_ex2(__ldg(lrow + lane + 32 * j));
        s += e[j];
    }
    #pragma unroll
    for (int sh = 16; sh > 0; sh >>= 1)
        s += __shfl_xor_sync(0xffffffffu, s, sh);
    float inv = __fdividef(1.0f, s);
    #pragma unroll
    for (int j = 0; j < 8; j++)
        out[row * UU + lane + 32 * j] = e[j] * inv;
}

// ---------------------------------------------------------------------------
extern "C" void kernel_launch(void* const* d_in, const int* in_sizes, int n_in,
                              void* d_out, int out_size) {
    const float* x    = (const float*)d_in[0];
    const float* W    = (const float*)d_in[1];
    const float* bias = (const float*)d_in[2];
    float* out = (float*)d_out;

    cudaFuncSetAttribute(gemm_kernel,
                         cudaFuncAttributeMaxDynamicSharedMemorySize, GEMM_SMEM);

    prep_kernel<<<512, 256>>>(x, W, bias);
    gemm_kernel<<<dim3(4, 32), 256, GEMM_SMEM>>>();
    softmax_kernel<<<BB / 8, 256>>>(out);
}